// round 1
// baseline (speedup 1.0000x reference)
#include <cuda_runtime.h>
#include <math.h>

#define NMAX 100000
#define EMAX 1600000
#define BN_EPS 1e-5f

// ---------------- device scratch (allowed: __device__ globals) ----------------
__device__ int   g_is64;
__device__ int   g_src[EMAX];
__device__ int   g_dst[EMAX];
__device__ int   g_deg[NMAX];
__device__ float g_dinv[NMAX];
__device__ int   g_rowptr[NMAX + 1];
__device__ int   g_cursor[NMAX];
__device__ int   g_col[EMAX + NMAX];
__device__ float g_ewt[EMAX + NMAX];
__device__ float g_h0[(size_t)NMAX * 64];
__device__ float g_t [(size_t)NMAX * 128];
__device__ float g_h [(size_t)NMAX * 128];

// ---------------- preprocessing kernels ----------------

// Detect whether edge_index buffer is int64 or int32.
// If int64 (little endian), every odd uint32 word is the (zero) high half.
__global__ void k_detect(const void* eidx) {
    if (threadIdx.x == 0 && blockIdx.x == 0) {
        const unsigned int* p = (const unsigned int*)eidx;
        int is64 = 1;
        for (int i = 0; i < 32; i++) {
            if (p[2 * i + 1] != 0u) { is64 = 0; break; }
        }
        g_is64 = is64;
    }
}

__global__ void k_convert(const void* eidx, int E) {
    int i = blockIdx.x * blockDim.x + threadIdx.x;
    if (i >= E) return;
    if (g_is64) {
        const long long* p = (const long long*)eidx;
        g_src[i] = (int)p[i];
        g_dst[i] = (int)p[(size_t)E + i];
    } else {
        const int* p = (const int*)eidx;
        g_src[i] = p[i];
        g_dst[i] = p[E + i];
    }
}

__global__ void k_zero_deg(int n) {
    int i = blockIdx.x * blockDim.x + threadIdx.x;
    if (i < n) g_deg[i] = 0;
}

__global__ void k_count(int E) {
    int i = blockIdx.x * blockDim.x + threadIdx.x;
    if (i < E) atomicAdd(&g_deg[g_dst[i]], 1);
}

__global__ void k_dinv(int n) {
    int i = blockIdx.x * blockDim.x + threadIdx.x;
    if (i < n) {
        // self-loop guarantees deg >= 1
        g_dinv[i] = rsqrtf((float)(g_deg[i] + 1));
    }
}

// single-block exclusive scan of (deg[i]+1) -> rowptr
__global__ void k_scan(int n) {
    __shared__ int s[1024];
    int t = threadIdx.x;
    int chunk = (n + 1023) / 1024;
    int lo = t * chunk;
    int hi = lo + chunk; if (hi > n) hi = n;
    int sum = 0;
    if (lo < n) for (int i = lo; i < hi; i++) sum += g_deg[i] + 1;
    s[t] = sum;
    __syncthreads();
    for (int d = 1; d < 1024; d <<= 1) {
        int v = 0;
        if (t >= d) v = s[t - d];
        __syncthreads();
        s[t] += v;
        __syncthreads();
    }
    int off = (t == 0) ? 0 : s[t - 1];
    if (lo < n) {
        int run = off;
        for (int i = lo; i < hi; i++) {
            g_rowptr[i] = run;
            run += g_deg[i] + 1;
        }
    }
    if (t == 1023) g_rowptr[n] = s[1023];
}

__global__ void k_cursor(int n) {
    int i = blockIdx.x * blockDim.x + threadIdx.x;
    if (i < n) g_cursor[i] = g_rowptr[i];
}

__global__ void k_fill_edges(int E) {
    int e = blockIdx.x * blockDim.x + threadIdx.x;
    if (e >= E) return;
    int s = g_src[e], d = g_dst[e];
    int pos = atomicAdd(&g_cursor[d], 1);
    g_col[pos] = s;
    g_ewt[pos] = g_dinv[s] * g_dinv[d];
}

__global__ void k_fill_loops(int n) {
    int i = blockIdx.x * blockDim.x + threadIdx.x;
    if (i >= n) return;
    int pos = atomicAdd(&g_cursor[i], 1);
    g_col[pos] = i;
    float di = g_dinv[i];
    g_ewt[pos] = di * di;
}

// ---------------- GEMM: C[n,FOUT] = A[n,FIN] @ W[FIN,FOUT] (+ epilogue) -------
// EPI: 0 = none, 1 = bias+relu, 2 = bias+bn+relu
template <int FIN, int FOUT, int EPI>
__global__ __launch_bounds__(256) void k_gemm(
    const float* __restrict__ A, const float* __restrict__ W,
    const float* __restrict__ bias,
    const float* __restrict__ gm, const float* __restrict__ bt,
    const float* __restrict__ mn, const float* __restrict__ vr,
    float* __restrict__ C, int n)
{
    constexpr int BM = 64, KC = 32;
    constexpr int NTC = FOUT / 4;        // threads along cols
    constexpr int NTR = 256 / NTC;       // threads along rows
    constexpr int TM  = BM / NTR;        // rows per thread

    __shared__ float As[BM][KC + 1];
    __shared__ float Ws[KC][FOUT];

    int tid = threadIdx.x;
    int rowBase = blockIdx.x * BM;
    int colT = tid % NTC;
    int rowT = tid / NTC;
    int col0 = colT * 4;

    float acc[TM][4];
    #pragma unroll
    for (int r = 0; r < TM; r++)
        #pragma unroll
        for (int c = 0; c < 4; c++) acc[r][c] = 0.f;

    for (int k0 = 0; k0 < FIN; k0 += KC) {
        // A tile: 64x32 = 512 float4, 2 per thread
        #pragma unroll
        for (int j = 0; j < 2; j++) {
            int idx = tid + 256 * j;
            int r = idx >> 3, c4 = idx & 7;
            int grow = rowBase + r;
            float4 v = make_float4(0.f, 0.f, 0.f, 0.f);
            if (grow < n)
                v = *reinterpret_cast<const float4*>(&A[(size_t)grow * FIN + k0 + c4 * 4]);
            As[r][c4 * 4 + 0] = v.x;
            As[r][c4 * 4 + 1] = v.y;
            As[r][c4 * 4 + 2] = v.z;
            As[r][c4 * 4 + 3] = v.w;
        }
        // W tile: KC x FOUT
        constexpr int WV = KC * FOUT / 4;
        #pragma unroll
        for (int j = 0; j < WV / 256; j++) {
            int idx = tid + 256 * j;
            int r = idx / (FOUT / 4), c4 = idx % (FOUT / 4);
            float4 v = *reinterpret_cast<const float4*>(&W[(size_t)(k0 + r) * FOUT + c4 * 4]);
            *reinterpret_cast<float4*>(&Ws[r][c4 * 4]) = v;
        }
        __syncthreads();
        #pragma unroll
        for (int kk = 0; kk < KC; kk++) {
            float4 w4 = *reinterpret_cast<const float4*>(&Ws[kk][col0]);
            #pragma unroll
            for (int r = 0; r < TM; r++) {
                float a = As[rowT * TM + r][kk];
                acc[r][0] += a * w4.x;
                acc[r][1] += a * w4.y;
                acc[r][2] += a * w4.z;
                acc[r][3] += a * w4.w;
            }
        }
        __syncthreads();
    }

    // epilogue parameters for this thread's 4 columns
    float s[4] = {1.f, 1.f, 1.f, 1.f};
    float t[4] = {0.f, 0.f, 0.f, 0.f};
    if constexpr (EPI == 1) {
        #pragma unroll
        for (int c = 0; c < 4; c++) t[c] = bias[col0 + c];
    } else if constexpr (EPI == 2) {
        #pragma unroll
        for (int c = 0; c < 4; c++) {
            int cc = col0 + c;
            float sc = gm[cc] * rsqrtf(vr[cc] + BN_EPS);
            s[c] = sc;
            t[c] = (bias[cc] - mn[cc]) * sc + bt[cc];
        }
    }

    #pragma unroll
    for (int r = 0; r < TM; r++) {
        int grow = rowBase + rowT * TM + r;
        if (grow >= n) continue;
        float4 st;
        float v0 = acc[r][0] * s[0] + t[0];
        float v1 = acc[r][1] * s[1] + t[1];
        float v2 = acc[r][2] * s[2] + t[2];
        float v3 = acc[r][3] * s[3] + t[3];
        if constexpr (EPI != 0) {
            v0 = fmaxf(v0, 0.f); v1 = fmaxf(v1, 0.f);
            v2 = fmaxf(v2, 0.f); v3 = fmaxf(v3, 0.f);
        }
        st.x = v0; st.y = v1; st.z = v2; st.w = v3;
        *reinterpret_cast<float4*>(&C[(size_t)grow * FOUT + col0]) = st;
    }
}

// ---------------- aggregation: O[i] = sum_e w[e]*H[col[e]] (+ optional epi) ---
// EPI: 0 = none, 1 = bias+bn+relu
template <int FW, int EPI>
__global__ void k_agg(const float* __restrict__ H, float* __restrict__ O,
                      const float* __restrict__ b,
                      const float* __restrict__ gm, const float* __restrict__ bt,
                      const float* __restrict__ mn, const float* __restrict__ vr,
                      int n)
{
    int i = blockIdx.x;
    if (i >= n) return;
    int f = threadIdx.x;
    int s = g_rowptr[i], e = g_rowptr[i + 1];
    float acc = 0.f;
    int p = s;
    for (; p + 4 <= e; p += 4) {
        int c0 = g_col[p], c1 = g_col[p + 1], c2 = g_col[p + 2], c3 = g_col[p + 3];
        float w0 = g_ewt[p], w1 = g_ewt[p + 1], w2 = g_ewt[p + 2], w3 = g_ewt[p + 3];
        float h0 = H[(size_t)c0 * FW + f];
        float h1 = H[(size_t)c1 * FW + f];
        float h2 = H[(size_t)c2 * FW + f];
        float h3 = H[(size_t)c3 * FW + f];
        acc += w0 * h0 + w1 * h1 + w2 * h2 + w3 * h3;
    }
    for (; p < e; ++p) acc += g_ewt[p] * H[(size_t)g_col[p] * FW + f];

    if constexpr (EPI == 1) {
        float sc = gm[f] * rsqrtf(vr[f] + BN_EPS);
        float val = (acc + b[f] - mn[f]) * sc + bt[f];
        O[(size_t)i * FW + f] = fmaxf(val, 0.f);
    } else {
        O[(size_t)i * FW + f] = acc;
    }
}

// ---------------- final: logits = H @ w_out + b_out; log_softmax -------------
__global__ __launch_bounds__(256) void k_out(
    const float* __restrict__ H, const float* __restrict__ Wo,
    const float* __restrict__ bo, float* __restrict__ out, int n)
{
    __shared__ float wsT[8 * 64];   // [c][f]
    __shared__ float bsh[8];
    int tid = threadIdx.x;
    for (int idx = tid; idx < 512; idx += 256) {
        int f = idx >> 3, c = idx & 7;
        wsT[c * 64 + f] = Wo[idx];
    }
    if (tid < 8) bsh[tid] = bo[tid];
    __syncthreads();

    int warp = tid >> 5, lane = tid & 31;
    int node = blockIdx.x * 8 + warp;
    if (node >= n) return;

    float ha = H[(size_t)node * 64 + lane];
    float hb = H[(size_t)node * 64 + 32 + lane];
    float l[8];
    #pragma unroll
    for (int c = 0; c < 8; c++) {
        float p = ha * wsT[c * 64 + lane] + hb * wsT[c * 64 + 32 + lane];
        #pragma unroll
        for (int off = 16; off; off >>= 1) p += __shfl_xor_sync(0xffffffff, p, off);
        l[c] = p + bsh[c];
    }
    float mx = l[0];
    #pragma unroll
    for (int c = 1; c < 8; c++) mx = fmaxf(mx, l[c]);
    float se = 0.f;
    #pragma unroll
    for (int c = 0; c < 8; c++) se += expf(l[c] - mx);
    float lse = mx + logf(se);
    if (lane < 8) out[(size_t)node * 8 + lane] = l[lane] - lse;
}

// ---------------- host ----------------
extern "C" void kernel_launch(void* const* d_in, const int* in_sizes, int n_in,
                              void* d_out, int out_size)
{
    int n = in_sizes[0] / 128;     // x: [N,128]
    int E = in_sizes[1] / 2;       // edge_index: [2,E]

    // Input ordering: dict-insertion order has w2 (16384 elems) at slot 6;
    // signature order has g1 (128 elems) there.
    bool dictOrder = in_sizes[6] > 512;

    const float* x    = (const float*)d_in[0];
    const void*  eidx = d_in[1];
    const float* w_in = (const float*)d_in[2];
    const float* b_in = (const float*)d_in[3];
    const float* w1   = (const float*)d_in[4];
    const float* b1   = (const float*)d_in[5];
    const float *w2, *b2, *w3, *b3, *w_out, *b_out;
    const float *G1, *BE1, *M1, *V1, *G2, *BE2, *M2, *V2, *G3, *BE3, *M3, *V3;
    if (dictOrder) {
        w2 = (const float*)d_in[6];  b2 = (const float*)d_in[7];
        w3 = (const float*)d_in[8];  b3 = (const float*)d_in[9];
        w_out = (const float*)d_in[10]; b_out = (const float*)d_in[11];
        G1 = (const float*)d_in[12]; BE1 = (const float*)d_in[13];
        M1 = (const float*)d_in[14]; V1  = (const float*)d_in[15];
        G2 = (const float*)d_in[16]; BE2 = (const float*)d_in[17];
        M2 = (const float*)d_in[18]; V2  = (const float*)d_in[19];
        G3 = (const float*)d_in[20]; BE3 = (const float*)d_in[21];
        M3 = (const float*)d_in[22]; V3  = (const float*)d_in[23];
    } else {
        G1 = (const float*)d_in[6];  BE1 = (const float*)d_in[7];
        M1 = (const float*)d_in[8];  V1  = (const float*)d_in[9];
        w2 = (const float*)d_in[10]; b2  = (const float*)d_in[11];
        G2 = (const float*)d_in[12]; BE2 = (const float*)d_in[13];
        M2 = (const float*)d_in[14]; V2  = (const float*)d_in[15];
        w3 = (const float*)d_in[16]; b3  = (const float*)d_in[17];
        G3 = (const float*)d_in[18]; BE3 = (const float*)d_in[19];
        M3 = (const float*)d_in[20]; V3  = (const float*)d_in[21];
        w_out = (const float*)d_in[22]; b_out = (const float*)d_in[23];
    }

    float *h0p, *tp, *hp;
    cudaGetSymbolAddress((void**)&h0p, g_h0);
    cudaGetSymbolAddress((void**)&tp,  g_t);
    cudaGetSymbolAddress((void**)&hp,  g_h);

    const int TB = 256;
    int gbE = (E + TB - 1) / TB;
    int gbN = (n + TB - 1) / TB;

    // ---- graph preprocessing: CSR with symmetric normalization ----
    k_detect<<<1, 32>>>(eidx);
    k_convert<<<gbE, TB>>>(eidx, E);
    k_zero_deg<<<gbN, TB>>>(n);
    k_count<<<gbE, TB>>>(E);
    k_dinv<<<gbN, TB>>>(n);
    k_scan<<<1, 1024>>>(n);
    k_cursor<<<gbN, TB>>>(n);
    k_fill_edges<<<gbE, TB>>>(E);
    k_fill_loops<<<gbN, TB>>>(n);

    int gbG = (n + 63) / 64;

    // h0 = relu(x @ w_in + b_in)                               [N,64]
    k_gemm<128, 64, 1><<<gbG, 256>>>(x, w_in, b_in,
                                     nullptr, nullptr, nullptr, nullptr, h0p, n);
    // t1 = A @ h0                                              [N,64]
    k_agg<64, 0><<<n, 64>>>(h0p, tp, nullptr, nullptr, nullptr, nullptr, nullptr, n);
    // h1 = relu(bn1(t1 @ w1 + b1))                             [N,128]
    k_gemm<64, 128, 2><<<gbG, 256>>>(tp, w1, b1, G1, BE1, M1, V1, hp, n);
    // t2 = A @ h1                                              [N,128]
    k_agg<128, 0><<<n, 128>>>(hp, tp, nullptr, nullptr, nullptr, nullptr, nullptr, n);
    // h2 = relu(bn2(t2 @ w2 + b2))                             [N,128]
    k_gemm<128, 128, 2><<<gbG, 256>>>(tp, w2, b2, G2, BE2, M2, V2, hp, n);
    // t3 = h2 @ w3  (no bias yet; bias applies after aggregation)  [N,64]
    k_gemm<128, 64, 0><<<gbG, 256>>>(hp, w3, nullptr,
                                     nullptr, nullptr, nullptr, nullptr, tp, n);
    // h3 = relu(bn3(A @ t3 + b3))                              [N,64]
    k_agg<64, 1><<<n, 64>>>(tp, hp, b3, G3, BE3, M3, V3, n);
    // out = log_softmax(h3 @ w_out + b_out)                    [N,8]
    k_out<<<(n + 7) / 8, 256>>>(hp, w_out, b_out, (float*)d_out, n);
}

// round 2
// speedup vs baseline: 1.1235x; 1.1235x over previous
#include <cuda_runtime.h>
#include <math.h>

#define NMAX 100000
#define EMAX 1600000
#define BN_EPS 1e-5f

// ---------------- device scratch ----------------
__device__ int   g_is64;
__device__ int   g_src[EMAX];
__device__ int   g_dstA[EMAX];
__device__ int   g_deg[NMAX];
__device__ float g_dinv[NMAX];
__device__ int   g_rowptr[NMAX + 1];
__device__ int   g_cursor[NMAX];
__device__ unsigned long long g_edge[EMAX + NMAX];   // low32 = col, high32 = weight bits
__device__ float g_h0[(size_t)NMAX * 64];
__device__ float g_t [(size_t)NMAX * 128];
__device__ float g_h [(size_t)NMAX * 128];

// ---------------- packed f32x2 helpers ----------------
__device__ __forceinline__ unsigned long long pk2(float x, float y) {
    unsigned long long r;
    asm("mov.b64 %0, {%1, %2};" : "=l"(r) : "f"(x), "f"(y));
    return r;
}
__device__ __forceinline__ void upk2(float& x, float& y, unsigned long long v) {
    asm("mov.b64 {%0, %1}, %2;" : "=f"(x), "=f"(y) : "l"(v));
}
#define FMA2(acc, a, b) asm("fma.rn.f32x2 %0, %1, %2, %0;" : "+l"(acc) : "l"(a), "l"(b))

// ---------------- preprocessing ----------------

// detect int64-vs-int32 edge_index AND zero degree array
__global__ void k_init(const void* eidx, int n) {
    int i = blockIdx.x * blockDim.x + threadIdx.x;
    if (i < n) g_deg[i] = 0;
    if (i == 0) {
        const unsigned int* p = (const unsigned int*)eidx;
        int is64 = 1;
        for (int k = 0; k < 32; k++)
            if (p[2 * k + 1] != 0u) { is64 = 0; break; }
        g_is64 = is64;
    }
}

// convert to int32 src/dst and count in-degree in one pass
__global__ void k_convert_count(const void* eidx, int E) {
    int i = blockIdx.x * blockDim.x + threadIdx.x;
    if (i >= E) return;
    int s, d;
    if (g_is64) {
        const long long* p = (const long long*)eidx;
        s = (int)p[i];
        d = (int)p[(size_t)E + i];
    } else {
        const int* p = (const int*)eidx;
        s = p[i];
        d = p[E + i];
    }
    g_src[i] = s;
    g_dstA[i] = d;
    atomicAdd(&g_deg[d], 1);
}

// single-block exclusive scan of (deg[i]+1) -> rowptr
__global__ void k_scan(int n) {
    __shared__ int s[1024];
    int t = threadIdx.x;
    int chunk = (n + 1023) / 1024;
    int lo = t * chunk;
    int hi = lo + chunk; if (hi > n) hi = n;
    int sum = 0;
    if (lo < n) for (int i = lo; i < hi; i++) sum += g_deg[i] + 1;
    s[t] = sum;
    __syncthreads();
    for (int d = 1; d < 1024; d <<= 1) {
        int v = 0;
        if (t >= d) v = s[t - d];
        __syncthreads();
        s[t] += v;
        __syncthreads();
    }
    int off = (t == 0) ? 0 : s[t - 1];
    if (lo < n) {
        int run = off;
        for (int i = lo; i < hi; i++) {
            g_rowptr[i] = run;
            run += g_deg[i] + 1;
        }
    }
    if (t == 1023) g_rowptr[n] = s[1023];
}

// per-node: dinv, cursor init, and place self-loop into last CSR slot
__global__ void k_node(int n) {
    int i = blockIdx.x * blockDim.x + threadIdx.x;
    if (i >= n) return;
    float di = rsqrtf((float)(g_deg[i] + 1));
    g_dinv[i] = di;
    g_cursor[i] = g_rowptr[i];
    int last = g_rowptr[i + 1] - 1;
    g_edge[last] = ((unsigned long long)__float_as_uint(di * di) << 32) |
                   (unsigned long long)(unsigned int)i;
}

__global__ void k_fill_edges(int E) {
    int e = blockIdx.x * blockDim.x + threadIdx.x;
    if (e >= E) return;
    int s = g_src[e], d = g_dstA[e];
    int pos = atomicAdd(&g_cursor[d], 1);
    float w = g_dinv[s] * g_dinv[d];
    g_edge[pos] = ((unsigned long long)__float_as_uint(w) << 32) |
                  (unsigned long long)(unsigned int)s;
}

// ---------------- GEMM: C[n,FOUT] = A[n,FIN] @ W[FIN,FOUT] (+ epilogue) -------
// EPI: 0 = none, 1 = bias+relu, 2 = bias+bn+relu
// Uses packed fma.rn.f32x2 (FFMA2): A tile stored duplicated {a,a} in smem.
template <int FIN, int FOUT, int EPI>
__global__ __launch_bounds__(256) void k_gemm(
    const float* __restrict__ A, const float* __restrict__ W,
    const float* __restrict__ bias,
    const float* __restrict__ gm, const float* __restrict__ bt,
    const float* __restrict__ mn, const float* __restrict__ vr,
    float* __restrict__ C, int n)
{
    constexpr int BM = 64, KC = 32;
    constexpr int NTC = FOUT / 4;        // thread cols (4 outputs each)
    constexpr int NTR = 256 / NTC;       // thread rows
    constexpr int TM  = BM / NTR;        // rows per thread

    __shared__ unsigned long long As2[BM][KC + 1];   // {a,a} duplicated pairs
    __shared__ float Ws[KC][FOUT];

    int tid = threadIdx.x;
    int rowBase = blockIdx.x * BM;
    int colT = tid % NTC;
    int rowT = tid / NTC;
    int col0 = colT * 4;

    unsigned long long acc2[TM][2];
    #pragma unroll
    for (int r = 0; r < TM; r++) { acc2[r][0] = 0ull; acc2[r][1] = 0ull; }

    for (int k0 = 0; k0 < FIN; k0 += KC) {
        // A tile: 64 rows x 32 cols, 2 float4 per thread, duplicated into pairs
        #pragma unroll
        for (int j = 0; j < 2; j++) {
            int idx = tid + 256 * j;
            int r = idx >> 3, c4 = idx & 7;
            int grow = rowBase + r;
            float4 v = make_float4(0.f, 0.f, 0.f, 0.f);
            if (grow < n)
                v = *reinterpret_cast<const float4*>(&A[(size_t)grow * FIN + k0 + c4 * 4]);
            As2[r][c4 * 4 + 0] = pk2(v.x, v.x);
            As2[r][c4 * 4 + 1] = pk2(v.y, v.y);
            As2[r][c4 * 4 + 2] = pk2(v.z, v.z);
            As2[r][c4 * 4 + 3] = pk2(v.w, v.w);
        }
        // W tile: KC x FOUT
        constexpr int WV = KC * FOUT / 4;
        #pragma unroll
        for (int j = 0; j < WV / 256; j++) {
            int idx = tid + 256 * j;
            int r = idx / (FOUT / 4), c4 = idx % (FOUT / 4);
            float4 v = *reinterpret_cast<const float4*>(&W[(size_t)(k0 + r) * FOUT + c4 * 4]);
            *reinterpret_cast<float4*>(&Ws[r][c4 * 4]) = v;
        }
        __syncthreads();
        #pragma unroll
        for (int kk = 0; kk < KC; kk++) {
            ulonglong2 wv = *reinterpret_cast<const ulonglong2*>(&Ws[kk][col0]);
            #pragma unroll
            for (int r = 0; r < TM; r++) {
                unsigned long long a2 = As2[rowT * TM + r][kk];
                FMA2(acc2[r][0], a2, wv.x);
                FMA2(acc2[r][1], a2, wv.y);
            }
        }
        __syncthreads();
    }

    // epilogue params for this thread's 4 columns
    float s[4] = {1.f, 1.f, 1.f, 1.f};
    float t[4] = {0.f, 0.f, 0.f, 0.f};
    if constexpr (EPI == 1) {
        #pragma unroll
        for (int c = 0; c < 4; c++) t[c] = bias[col0 + c];
    } else if constexpr (EPI == 2) {
        #pragma unroll
        for (int c = 0; c < 4; c++) {
            int cc = col0 + c;
            float sc = gm[cc] * rsqrtf(vr[cc] + BN_EPS);
            s[c] = sc;
            t[c] = (bias[cc] - mn[cc]) * sc + bt[cc];
        }
    }

    #pragma unroll
    for (int r = 0; r < TM; r++) {
        int grow = rowBase + rowT * TM + r;
        if (grow >= n) continue;
        float v0, v1, v2, v3;
        upk2(v0, v1, acc2[r][0]);
        upk2(v2, v3, acc2[r][1]);
        v0 = v0 * s[0] + t[0];
        v1 = v1 * s[1] + t[1];
        v2 = v2 * s[2] + t[2];
        v3 = v3 * s[3] + t[3];
        if constexpr (EPI != 0) {
            v0 = fmaxf(v0, 0.f); v1 = fmaxf(v1, 0.f);
            v2 = fmaxf(v2, 0.f); v3 = fmaxf(v3, 0.f);
        }
        float4 st; st.x = v0; st.y = v1; st.z = v2; st.w = v3;
        *reinterpret_cast<float4*>(&C[(size_t)grow * FOUT + col0]) = st;
    }
}

// ---------------- aggregation: O[i] = sum_e w[e]*H[col[e]] (+ optional epi) ---
// Packed: 2 feats per thread, FW/2 threads per node, block = 128 threads.
// EPI: 0 = none, 1 = bias+bn+relu
template <int FW, int EPI>
__global__ __launch_bounds__(128) void k_agg(
    const float* __restrict__ H, float* __restrict__ O,
    const float* __restrict__ b,
    const float* __restrict__ gm, const float* __restrict__ bt,
    const float* __restrict__ mn, const float* __restrict__ vr,
    int n)
{
    constexpr int TPN = FW / 2;            // threads per node
    constexpr int NPB = 128 / TPN;         // nodes per block
    int node = blockIdx.x * NPB + threadIdx.y;
    if (node >= n) return;
    int f2 = threadIdx.x;                  // feature pair index

    int s = g_rowptr[node], e = g_rowptr[node + 1];
    unsigned long long accA = 0ull, accB = 0ull;
    int p = s;
    for (; p + 2 <= e; p += 2) {
        unsigned long long e0 = g_edge[p];
        unsigned long long e1 = g_edge[p + 1];
        int c0 = (int)(unsigned int)e0;
        int c1 = (int)(unsigned int)e1;
        unsigned long long w0 = pk2(__uint_as_float((unsigned int)(e0 >> 32)),
                                    __uint_as_float((unsigned int)(e0 >> 32)));
        unsigned long long w1 = pk2(__uint_as_float((unsigned int)(e1 >> 32)),
                                    __uint_as_float((unsigned int)(e1 >> 32)));
        unsigned long long h0 = *reinterpret_cast<const unsigned long long*>(
            &H[(size_t)c0 * FW + 2 * f2]);
        unsigned long long h1 = *reinterpret_cast<const unsigned long long*>(
            &H[(size_t)c1 * FW + 2 * f2]);
        FMA2(accA, w0, h0);
        FMA2(accB, w1, h1);
    }
    if (p < e) {
        unsigned long long e0 = g_edge[p];
        int c0 = (int)(unsigned int)e0;
        float w = __uint_as_float((unsigned int)(e0 >> 32));
        unsigned long long w0 = pk2(w, w);
        unsigned long long h0 = *reinterpret_cast<const unsigned long long*>(
            &H[(size_t)c0 * FW + 2 * f2]);
        FMA2(accA, w0, h0);
    }

    float a0, a1, b0, b1;
    upk2(a0, a1, accA);
    upk2(b0, b1, accB);
    a0 += b0; a1 += b1;

    int f = 2 * f2;
    if constexpr (EPI == 1) {
        float sc0 = gm[f] * rsqrtf(vr[f] + BN_EPS);
        float sc1 = gm[f + 1] * rsqrtf(vr[f + 1] + BN_EPS);
        float v0 = (a0 + b[f] - mn[f]) * sc0 + bt[f];
        float v1 = (a1 + b[f + 1] - mn[f + 1]) * sc1 + bt[f + 1];
        float2 st; st.x = fmaxf(v0, 0.f); st.y = fmaxf(v1, 0.f);
        *reinterpret_cast<float2*>(&O[(size_t)node * FW + f]) = st;
    } else {
        float2 st; st.x = a0; st.y = a1;
        *reinterpret_cast<float2*>(&O[(size_t)node * FW + f]) = st;
    }
}

// ---------------- final: logits = H @ w_out + b_out; log_softmax -------------
__global__ __launch_bounds__(256) void k_out(
    const float* __restrict__ H, const float* __restrict__ Wo,
    const float* __restrict__ bo, float* __restrict__ out, int n)
{
    __shared__ float wsT[8 * 64];   // [c][f]
    __shared__ float bsh[8];
    int tid = threadIdx.x;
    for (int idx = tid; idx < 512; idx += 256) {
        int f = idx >> 3, c = idx & 7;
        wsT[c * 64 + f] = Wo[idx];
    }
    if (tid < 8) bsh[tid] = bo[tid];
    __syncthreads();

    int warp = tid >> 5, lane = tid & 31;
    int node = blockIdx.x * 8 + warp;
    if (node >= n) return;

    float ha = H[(size_t)node * 64 + lane];
    float hb = H[(size_t)node * 64 + 32 + lane];
    float l[8];
    #pragma unroll
    for (int c = 0; c < 8; c++) {
        float p = ha * wsT[c * 64 + lane] + hb * wsT[c * 64 + 32 + lane];
        #pragma unroll
        for (int off = 16; off; off >>= 1) p += __shfl_xor_sync(0xffffffff, p, off);
        l[c] = p + bsh[c];
    }
    float mx = l[0];
    #pragma unroll
    for (int c = 1; c < 8; c++) mx = fmaxf(mx, l[c]);
    float se = 0.f;
    #pragma unroll
    for (int c = 0; c < 8; c++) se += expf(l[c] - mx);
    float lse = mx + logf(se);
    if (lane < 8) out[(size_t)node * 8 + lane] = l[lane] - lse;
}

// ---------------- host ----------------
extern "C" void kernel_launch(void* const* d_in, const int* in_sizes, int n_in,
                              void* d_out, int out_size)
{
    int n = in_sizes[0] / 128;     // x: [N,128]
    int E = in_sizes[1] / 2;       // edge_index: [2,E]

    bool dictOrder = in_sizes[6] > 512;

    const float* x    = (const float*)d_in[0];
    const void*  eidx = d_in[1];
    const float* w_in = (const float*)d_in[2];
    const float* b_in = (const float*)d_in[3];
    const float* w1   = (const float*)d_in[4];
    const float* b1   = (const float*)d_in[5];
    const float *w2, *b2, *w3, *b3, *w_out, *b_out;
    const float *G1, *BE1, *M1, *V1, *G2, *BE2, *M2, *V2, *G3, *BE3, *M3, *V3;
    if (dictOrder) {
        w2 = (const float*)d_in[6];  b2 = (const float*)d_in[7];
        w3 = (const float*)d_in[8];  b3 = (const float*)d_in[9];
        w_out = (const float*)d_in[10]; b_out = (const float*)d_in[11];
        G1 = (const float*)d_in[12]; BE1 = (const float*)d_in[13];
        M1 = (const float*)d_in[14]; V1  = (const float*)d_in[15];
        G2 = (const float*)d_in[16]; BE2 = (const float*)d_in[17];
        M2 = (const float*)d_in[18]; V2  = (const float*)d_in[19];
        G3 = (const float*)d_in[20]; BE3 = (const float*)d_in[21];
        M3 = (const float*)d_in[22]; V3  = (const float*)d_in[23];
    } else {
        G1 = (const float*)d_in[6];  BE1 = (const float*)d_in[7];
        M1 = (const float*)d_in[8];  V1  = (const float*)d_in[9];
        w2 = (const float*)d_in[10]; b2  = (const float*)d_in[11];
        G2 = (const float*)d_in[12]; BE2 = (const float*)d_in[13];
        M2 = (const float*)d_in[14]; V2  = (const float*)d_in[15];
        w3 = (const float*)d_in[16]; b3  = (const float*)d_in[17];
        G3 = (const float*)d_in[18]; BE3 = (const float*)d_in[19];
        M3 = (const float*)d_in[20]; V3  = (const float*)d_in[21];
        w_out = (const float*)d_in[22]; b_out = (const float*)d_in[23];
    }

    float *h0p, *tp, *hp;
    cudaGetSymbolAddress((void**)&h0p, g_h0);
    cudaGetSymbolAddress((void**)&tp,  g_t);
    cudaGetSymbolAddress((void**)&hp,  g_h);

    const int TB = 256;
    int gbE = (E + TB - 1) / TB;
    int gbN = (n + TB - 1) / TB;

    // ---- graph preprocessing: CSR w/ sym-norm, self-loop in last slot ----
    k_init<<<gbN, TB>>>(eidx, n);
    k_convert_count<<<gbE, TB>>>(eidx, E);
    k_scan<<<1, 1024>>>(n);
    k_node<<<gbN, TB>>>(n);
    k_fill_edges<<<gbE, TB>>>(E);

    int gbG = (n + 63) / 64;

    // h0 = relu(x @ w_in + b_in)                               [N,64]
    k_gemm<128, 64, 1><<<gbG, 256>>>(x, w_in, b_in,
                                     nullptr, nullptr, nullptr, nullptr, h0p, n);
    // t1 = A @ h0                                              [N,64]
    {
        dim3 blk(32, 4);
        k_agg<64, 0><<<(n + 3) / 4, blk>>>(h0p, tp, nullptr, nullptr, nullptr,
                                           nullptr, nullptr, n);
    }
    // h1 = relu(bn1(t1 @ w1 + b1))                             [N,128]
    k_gemm<64, 128, 2><<<gbG, 256>>>(tp, w1, b1, G1, BE1, M1, V1, hp, n);
    // t2 = A @ h1                                              [N,128]
    {
        dim3 blk(64, 2);
        k_agg<128, 0><<<(n + 1) / 2, blk>>>(hp, tp, nullptr, nullptr, nullptr,
                                            nullptr, nullptr, n);
    }
    // h2 = relu(bn2(t2 @ w2 + b2))                             [N,128]
    k_gemm<128, 128, 2><<<gbG, 256>>>(tp, w2, b2, G2, BE2, M2, V2, hp, n);
    // t3 = h2 @ w3                                             [N,64]
    k_gemm<128, 64, 0><<<gbG, 256>>>(hp, w3, nullptr,
                                     nullptr, nullptr, nullptr, nullptr, tp, n);
    // h3 = relu(bn3(A @ t3 + b3))                              [N,64]
    {
        dim3 blk(32, 4);
        k_agg<64, 1><<<(n + 3) / 4, blk>>>(tp, hp, b3, G3, BE3, M3, V3, n);
    }
    // out = log_softmax(h3 @ w_out + b_out)                    [N,8]
    k_out<<<(n + 7) / 8, 256>>>(hp, w_out, b_out, (float*)d_out, n);
}